// round 10
// baseline (speedup 1.0000x reference)
#include <cuda_runtime.h>
#include <cuda_fp16.h>
#include <cstdint>

// APPNP: h <- 0.9 * A@h + 0.1 * x, 10 iterations, edge-list A.
// CSR build, then 10x warp-per-row SpMM in fp16 storage (h_k scaled 4^-k).
// Gather: quarter-warp per edge, one 32-lane LDG.128 covers four 128B fp16
// rows. This round: software-pipelined (col,w) stream — the next step's cw
// load issues before the current gather, removing the serialized
// L_cw -> L_gather dependency chain — plus unroll 8 for deeper MLP.

#define N_NODES 100000
#define N_EDGES 3200000
#define D_FEAT  64
#define ALPHA   0.1f
#define K_STEPS 10
#define SCAN_BLK 1024
#define N_SCAN_BLKS ((N_NODES + SCAN_BLK - 1) / SCAN_BLK)   // 98
#define ROW_U4 (D_FEAT / 8)   // 8 uint4 (128B) per fp16 row

// -------- static device scratch (no allocations allowed) --------
__device__ int            g_count[N_NODES];
__device__ int            g_rowptr[N_NODES + 1];
__device__ int            g_bsum[N_SCAN_BLKS];
__device__ int            g_boff[N_SCAN_BLKS];
__device__ unsigned short g_rank[N_EDGES];
__device__ int2           g_cw[N_EDGES];                    // {col, bits(0.9*w)}
__device__ uint4          g_hA[(size_t)N_NODES * ROW_U4];   // fp16 h ping
__device__ uint4          g_hB[(size_t)N_NODES * ROW_U4];   // fp16 h pong
__device__ uint4          g_x16[(size_t)N_NODES * ROW_U4];  // fp16 copy of x

// -------- CSR build --------
__global__ void k_hist(const int4* __restrict__ erow4) {
    int t = blockIdx.x * blockDim.x + threadIdx.x;
    if (t < N_EDGES / 4) {
        int4 r = erow4[t];
        unsigned short r0 = (unsigned short)atomicAdd(&g_count[r.x], 1);
        unsigned short r1 = (unsigned short)atomicAdd(&g_count[r.y], 1);
        unsigned short r2 = (unsigned short)atomicAdd(&g_count[r.z], 1);
        unsigned short r3 = (unsigned short)atomicAdd(&g_count[r.w], 1);
        ((ushort4*)g_rank)[t] = make_ushort4(r0, r1, r2, r3);
    }
}

__global__ void __launch_bounds__(SCAN_BLK) k_scan1() {
    __shared__ int s[SCAN_BLK];
    int tid = threadIdx.x;
    int i = blockIdx.x * SCAN_BLK + tid;
    int v = (i < N_NODES) ? g_count[i] : 0;
    s[tid] = v;
    __syncthreads();
    #pragma unroll
    for (int off = 1; off < SCAN_BLK; off <<= 1) {
        int t = (tid >= off) ? s[tid - off] : 0;
        __syncthreads();
        s[tid] += t;
        __syncthreads();
    }
    if (i < N_NODES) g_rowptr[i] = s[tid] - v;
    if (tid == SCAN_BLK - 1) g_bsum[blockIdx.x] = s[tid];
}

__global__ void k_scan2() {
    __shared__ int s[128];
    int tid = threadIdx.x;
    int v = (tid < N_SCAN_BLKS) ? g_bsum[tid] : 0;
    s[tid] = v;
    __syncthreads();
    #pragma unroll
    for (int off = 1; off < 128; off <<= 1) {
        int t = (tid >= off) ? s[tid - off] : 0;
        __syncthreads();
        s[tid] += t;
        __syncthreads();
    }
    if (tid < N_SCAN_BLKS) g_boff[tid] = s[tid] - v;
    if (tid == 0) g_rowptr[N_NODES] = N_EDGES;
}

__global__ void k_scan3() {
    int i = blockIdx.x * blockDim.x + threadIdx.x;
    if (i < N_NODES) g_rowptr[i] += g_boff[i >> 10];
}

__global__ void k_scatter(const int4* __restrict__ erow4,
                          const int4* __restrict__ ecol4,
                          const float4* __restrict__ ew4) {
    int t = blockIdx.x * blockDim.x + threadIdx.x;
    if (t < N_EDGES / 4) {
        int4    r  = erow4[t];
        int4    c  = ecol4[t];
        float4  w  = ew4[t];
        ushort4 rk = ((const ushort4*)g_rank)[t];
        const float s = 1.0f - ALPHA;
        g_cw[g_rowptr[r.x] + rk.x] = make_int2(c.x, __float_as_int(s * w.x));
        g_cw[g_rowptr[r.y] + rk.y] = make_int2(c.y, __float_as_int(s * w.y));
        g_cw[g_rowptr[r.z] + rk.z] = make_int2(c.z, __float_as_int(s * w.z));
        g_cw[g_rowptr[r.w] + rk.w] = make_int2(c.w, __float_as_int(s * w.w));
    }
}

// -------- x (fp32) -> fp16 --------
__global__ void k_cvt(const float4* __restrict__ xin) {
    int t = blockIdx.x * blockDim.x + threadIdx.x;
    if (t < N_NODES * D_FEAT / 8) {
        float4 a = xin[2 * t], b = xin[2 * t + 1];
        uint4 pk;
        *(__half2*)&pk.x = __floats2half2_rn(a.x, a.y);
        *(__half2*)&pk.y = __floats2half2_rn(a.z, a.w);
        *(__half2*)&pk.z = __floats2half2_rn(b.x, b.y);
        *(__half2*)&pk.w = __floats2half2_rn(b.z, b.w);
        g_x16[t] = pk;
    }
}

// -------- SpMM: warp per row; quarter-warp per edge; pipelined cw ---------
// src stored fp16 at scale c_in; writes dst at scale c_out.
// k1 = c_out/c_in, k2 = 0.1*c_out.
template<bool DST_F16>
__global__ void __launch_bounds__(256)
k_spmm16(const uint4* __restrict__ src, const float* __restrict__ x,
         void* __restrict__ dst, float k1, float k2) {
    int warp = (blockIdx.x * blockDim.x + threadIdx.x) >> 5;
    int lane = threadIdx.x & 31;
    if (warp >= N_NODES) return;

    int q = lane >> 3;   // quarter: which edge within each 4-edge step
    int p = lane & 7;    // feature group: feats p*8 .. p*8+7

    int beg = g_rowptr[warp];
    int end = g_rowptr[warp + 1];
    int len = end - beg;
    int n   = (len > q) ? ((len - q + 3) >> 2) : 0;   // steps for this quarter

    float acc0 = 0.f, acc1 = 0.f, acc2 = 0.f, acc3 = 0.f;
    float acc4 = 0.f, acc5 = 0.f, acc6 = 0.f, acc7 = 0.f;

    int e = beg + q;
    int2 cw = (n > 0) ? g_cw[e] : make_int2(0, 0);

    #pragma unroll 8
    for (int s = 0; s < n; s++) {
        // prefetch next step's (col,w) before consuming the current one
        int2 cw_n = (s + 1 < n) ? g_cw[e + 4] : make_int2(0, 0);
        float w  = __int_as_float(cw.y);
        uint4 hv = src[(size_t)cw.x * ROW_U4 + p]; // 16B of one fp16 row
        float2 f0 = __half22float2(*(const __half2*)&hv.x);
        float2 f1 = __half22float2(*(const __half2*)&hv.y);
        float2 f2 = __half22float2(*(const __half2*)&hv.z);
        float2 f3 = __half22float2(*(const __half2*)&hv.w);
        acc0 = fmaf(w, f0.x, acc0); acc1 = fmaf(w, f0.y, acc1);
        acc2 = fmaf(w, f1.x, acc2); acc3 = fmaf(w, f1.y, acc3);
        acc4 = fmaf(w, f2.x, acc4); acc5 = fmaf(w, f2.y, acc5);
        acc6 = fmaf(w, f3.x, acc6); acc7 = fmaf(w, f3.y, acc7);
        cw = cw_n;
        e += 4;
    }

    // combine the 4 quarters (disjoint edge subsets, same feature layout)
    #pragma unroll
    for (int d = 8; d <= 16; d <<= 1) {
        acc0 += __shfl_xor_sync(0xffffffffu, acc0, d);
        acc1 += __shfl_xor_sync(0xffffffffu, acc1, d);
        acc2 += __shfl_xor_sync(0xffffffffu, acc2, d);
        acc3 += __shfl_xor_sync(0xffffffffu, acc3, d);
        acc4 += __shfl_xor_sync(0xffffffffu, acc4, d);
        acc5 += __shfl_xor_sync(0xffffffffu, acc5, d);
        acc6 += __shfl_xor_sync(0xffffffffu, acc6, d);
        acc7 += __shfl_xor_sync(0xffffffffu, acc7, d);
    }

    if (lane < 8) {
        const float4* xv = (const float4*)(x + (size_t)warp * D_FEAT + p * 8);
        float4 xa = xv[0], xb = xv[1];
        float o0 = fmaf(k2, xa.x, k1 * acc0);
        float o1 = fmaf(k2, xa.y, k1 * acc1);
        float o2 = fmaf(k2, xa.z, k1 * acc2);
        float o3 = fmaf(k2, xa.w, k1 * acc3);
        float o4 = fmaf(k2, xb.x, k1 * acc4);
        float o5 = fmaf(k2, xb.y, k1 * acc5);
        float o6 = fmaf(k2, xb.z, k1 * acc6);
        float o7 = fmaf(k2, xb.w, k1 * acc7);
        if (DST_F16) {
            uint4 pk;
            *(__half2*)&pk.x = __floats2half2_rn(o0, o1);
            *(__half2*)&pk.y = __floats2half2_rn(o2, o3);
            *(__half2*)&pk.z = __floats2half2_rn(o4, o5);
            *(__half2*)&pk.w = __floats2half2_rn(o6, o7);
            ((uint4*)dst)[(size_t)warp * ROW_U4 + p] = pk;
        } else {
            float4* d = (float4*)((float*)dst + (size_t)warp * D_FEAT + p * 8);
            d[0] = make_float4(o0, o1, o2, o3);
            d[1] = make_float4(o4, o5, o6, o7);
        }
    }
}

extern "C" void kernel_launch(void* const* d_in, const int* in_sizes, int n_in,
                              void* d_out, int out_size) {
    const float* x    = (const float*)d_in[0];
    const int*   erow = (const int*)d_in[1];
    const int*   ecol = (const int*)d_in[2];
    const float* ew   = (const float*)d_in[3];
    float*       out  = (float*)d_out;

    uint4 *hA, *hB, *x16;
    int* countPtr;
    cudaGetSymbolAddress((void**)&hA, g_hA);
    cudaGetSymbolAddress((void**)&hB, g_hB);
    cudaGetSymbolAddress((void**)&x16, g_x16);
    cudaGetSymbolAddress((void**)&countPtr, g_count);

    const int TB = 256;
    const int nodeBlocks = (N_NODES + TB - 1) / TB;
    const int quadBlocks = (N_EDGES / 4 + TB - 1) / TB;
    const int cvtBlocks  = (N_NODES * D_FEAT / 8 + TB - 1) / TB;
    const int spmmBlocks = (N_NODES * 32 + TB - 1) / TB;

    // CSR build
    cudaMemsetAsync(countPtr, 0, N_NODES * sizeof(int));
    k_hist<<<quadBlocks, TB>>>((const int4*)erow);
    k_scan1<<<N_SCAN_BLKS, SCAN_BLK>>>();
    k_scan2<<<1, 128>>>();
    k_scan3<<<nodeBlocks, TB>>>();
    k_scatter<<<quadBlocks, TB>>>((const int4*)erow, (const int4*)ecol,
                                  (const float4*)ew);
    k_cvt<<<cvtBlocks, TB>>>((const float4*)x);

    // 10 propagation steps, all fp16 storage, scale c_k = 4^-k (c_10 = 1).
    const uint4* src = x16;
    uint4* bufs[2] = { hA, hB };
    for (int k = 1; k <= K_STEPS; k++) {
        if (k < K_STEPS) {
            float c_k = exp2f(-2.0f * k);
            uint4* dst = bufs[k & 1];
            k_spmm16<true><<<spmmBlocks, TB>>>(src, x, dst, 0.25f, 0.1f * c_k);
            src = dst;
        } else {
            float k1 = exp2f(2.0f * (K_STEPS - 1));   // 1/c_9 = 2^18
            k_spmm16<false><<<spmmBlocks, TB>>>(src, x, out, k1, 0.1f);
        }
    }
}

// round 11
// speedup vs baseline: 1.1934x; 1.1934x over previous
#include <cuda_runtime.h>
#include <cuda_fp16.h>
#include <cstdint>

// APPNP: h <- 0.9 * A@h + 0.1 * x, 10 iterations, edge-list A.
// CSR build, then 10x warp-per-row SpMM in fp16 storage (h_k scaled 4^-k).
// Gather: quarter-warp per edge, one 32-lane LDG.128 covers four 128B fp16
// rows. Edge entries packed to 4B: col(17b) | fixed-point 0.9*w (15b) —
// halves the cw stream traffic. Loop restored to the R9 form (compiler
// front-batches independent LDGs; manual pipelining regressed).

#define N_NODES 100000
#define N_EDGES 3200000
#define D_FEAT  64
#define ALPHA   0.1f
#define K_STEPS 10
#define SCAN_BLK 1024
#define N_SCAN_BLKS ((N_NODES + SCAN_BLK - 1) / SCAN_BLK)   // 98
#define ROW_U4 (D_FEAT / 8)   // 8 uint4 (128B) per fp16 row
#define W_SCALE 32768.0f
#define W_INV   (1.0f / 32768.0f)

// -------- static device scratch (no allocations allowed) --------
__device__ int            g_count[N_NODES];
__device__ int            g_rowptr[N_NODES + 1];
__device__ int            g_bsum[N_SCAN_BLKS];
__device__ int            g_boff[N_SCAN_BLKS];
__device__ unsigned short g_rank[N_EDGES];
__device__ unsigned int   g_cwp[N_EDGES];                   // col<<15 | wfix15
__device__ uint4          g_hA[(size_t)N_NODES * ROW_U4];   // fp16 h ping
__device__ uint4          g_hB[(size_t)N_NODES * ROW_U4];   // fp16 h pong
__device__ uint4          g_x16[(size_t)N_NODES * ROW_U4];  // fp16 copy of x

// -------- CSR build --------
__global__ void k_hist(const int4* __restrict__ erow4) {
    int t = blockIdx.x * blockDim.x + threadIdx.x;
    if (t < N_EDGES / 4) {
        int4 r = erow4[t];
        unsigned short r0 = (unsigned short)atomicAdd(&g_count[r.x], 1);
        unsigned short r1 = (unsigned short)atomicAdd(&g_count[r.y], 1);
        unsigned short r2 = (unsigned short)atomicAdd(&g_count[r.z], 1);
        unsigned short r3 = (unsigned short)atomicAdd(&g_count[r.w], 1);
        ((ushort4*)g_rank)[t] = make_ushort4(r0, r1, r2, r3);
    }
}

__global__ void __launch_bounds__(SCAN_BLK) k_scan1() {
    __shared__ int s[SCAN_BLK];
    int tid = threadIdx.x;
    int i = blockIdx.x * SCAN_BLK + tid;
    int v = (i < N_NODES) ? g_count[i] : 0;
    s[tid] = v;
    __syncthreads();
    #pragma unroll
    for (int off = 1; off < SCAN_BLK; off <<= 1) {
        int t = (tid >= off) ? s[tid - off] : 0;
        __syncthreads();
        s[tid] += t;
        __syncthreads();
    }
    if (i < N_NODES) g_rowptr[i] = s[tid] - v;
    if (tid == SCAN_BLK - 1) g_bsum[blockIdx.x] = s[tid];
}

__global__ void k_scan2() {
    __shared__ int s[128];
    int tid = threadIdx.x;
    int v = (tid < N_SCAN_BLKS) ? g_bsum[tid] : 0;
    s[tid] = v;
    __syncthreads();
    #pragma unroll
    for (int off = 1; off < 128; off <<= 1) {
        int t = (tid >= off) ? s[tid - off] : 0;
        __syncthreads();
        s[tid] += t;
        __syncthreads();
    }
    if (tid < N_SCAN_BLKS) g_boff[tid] = s[tid] - v;
    if (tid == 0) g_rowptr[N_NODES] = N_EDGES;
}

__global__ void k_scan3() {
    int i = blockIdx.x * blockDim.x + threadIdx.x;
    if (i < N_NODES) g_rowptr[i] += g_boff[i >> 10];
}

__global__ void k_scatter(const int4* __restrict__ erow4,
                          const int4* __restrict__ ecol4,
                          const float4* __restrict__ ew4) {
    int t = blockIdx.x * blockDim.x + threadIdx.x;
    if (t < N_EDGES / 4) {
        int4    r  = erow4[t];
        int4    c  = ecol4[t];
        float4  w  = ew4[t];
        ushort4 rk = ((const ushort4*)g_rank)[t];
        const float s = (1.0f - ALPHA) * W_SCALE;
        unsigned int w0 = (unsigned int)__float2int_rn(s * w.x);
        unsigned int w1 = (unsigned int)__float2int_rn(s * w.y);
        unsigned int w2 = (unsigned int)__float2int_rn(s * w.z);
        unsigned int w3 = (unsigned int)__float2int_rn(s * w.w);
        g_cwp[g_rowptr[r.x] + rk.x] = ((unsigned int)c.x << 15) | w0;
        g_cwp[g_rowptr[r.y] + rk.y] = ((unsigned int)c.y << 15) | w1;
        g_cwp[g_rowptr[r.z] + rk.z] = ((unsigned int)c.z << 15) | w2;
        g_cwp[g_rowptr[r.w] + rk.w] = ((unsigned int)c.w << 15) | w3;
    }
}

// -------- x (fp32) -> fp16 --------
__global__ void k_cvt(const float4* __restrict__ xin) {
    int t = blockIdx.x * blockDim.x + threadIdx.x;
    if (t < N_NODES * D_FEAT / 8) {
        float4 a = xin[2 * t], b = xin[2 * t + 1];
        uint4 pk;
        *(__half2*)&pk.x = __floats2half2_rn(a.x, a.y);
        *(__half2*)&pk.y = __floats2half2_rn(a.z, a.w);
        *(__half2*)&pk.z = __floats2half2_rn(b.x, b.y);
        *(__half2*)&pk.w = __floats2half2_rn(b.z, b.w);
        g_x16[t] = pk;
    }
}

// -------- SpMM: warp per row; quarter-warp per edge; LDG.128 gathers -------
// src stored fp16 at scale c_in; writes dst at scale c_out.
// k1 = c_out/c_in, k2 = 0.1*c_out.
template<bool DST_F16>
__global__ void __launch_bounds__(256)
k_spmm16(const uint4* __restrict__ src, const float* __restrict__ x,
         void* __restrict__ dst, float k1, float k2) {
    int warp = (blockIdx.x * blockDim.x + threadIdx.x) >> 5;
    int lane = threadIdx.x & 31;
    if (warp >= N_NODES) return;

    int q = lane >> 3;   // quarter: which edge within each 4-edge step
    int p = lane & 7;    // feature group: feats p*8 .. p*8+7

    int beg = g_rowptr[warp];
    int end = g_rowptr[warp + 1];

    float acc0 = 0.f, acc1 = 0.f, acc2 = 0.f, acc3 = 0.f;
    float acc4 = 0.f, acc5 = 0.f, acc6 = 0.f, acc7 = 0.f;

    #pragma unroll 4
    for (int e = beg + q; e < end; e += 4) {
        unsigned int cw = g_cwp[e];               // uniform per quarter
        unsigned int c  = cw >> 15;
        float w = (float)(int)(cw & 0x7fffu) * W_INV;   // carries (1-alpha)
        uint4 hv = src[(size_t)c * ROW_U4 + p];   // 16B of one fp16 row
        float2 f0 = __half22float2(*(const __half2*)&hv.x);
        float2 f1 = __half22float2(*(const __half2*)&hv.y);
        float2 f2 = __half22float2(*(const __half2*)&hv.z);
        float2 f3 = __half22float2(*(const __half2*)&hv.w);
        acc0 = fmaf(w, f0.x, acc0); acc1 = fmaf(w, f0.y, acc1);
        acc2 = fmaf(w, f1.x, acc2); acc3 = fmaf(w, f1.y, acc3);
        acc4 = fmaf(w, f2.x, acc4); acc5 = fmaf(w, f2.y, acc5);
        acc6 = fmaf(w, f3.x, acc6); acc7 = fmaf(w, f3.y, acc7);
    }

    // combine the 4 quarters (disjoint edge subsets, same feature layout)
    #pragma unroll
    for (int d = 8; d <= 16; d <<= 1) {
        acc0 += __shfl_xor_sync(0xffffffffu, acc0, d);
        acc1 += __shfl_xor_sync(0xffffffffu, acc1, d);
        acc2 += __shfl_xor_sync(0xffffffffu, acc2, d);
        acc3 += __shfl_xor_sync(0xffffffffu, acc3, d);
        acc4 += __shfl_xor_sync(0xffffffffu, acc4, d);
        acc5 += __shfl_xor_sync(0xffffffffu, acc5, d);
        acc6 += __shfl_xor_sync(0xffffffffu, acc6, d);
        acc7 += __shfl_xor_sync(0xffffffffu, acc7, d);
    }

    if (lane < 8) {
        const float4* xv = (const float4*)(x + (size_t)warp * D_FEAT + p * 8);
        float4 xa = xv[0], xb = xv[1];
        float o0 = fmaf(k2, xa.x, k1 * acc0);
        float o1 = fmaf(k2, xa.y, k1 * acc1);
        float o2 = fmaf(k2, xa.z, k1 * acc2);
        float o3 = fmaf(k2, xa.w, k1 * acc3);
        float o4 = fmaf(k2, xb.x, k1 * acc4);
        float o5 = fmaf(k2, xb.y, k1 * acc5);
        float o6 = fmaf(k2, xb.z, k1 * acc6);
        float o7 = fmaf(k2, xb.w, k1 * acc7);
        if (DST_F16) {
            uint4 pk;
            *(__half2*)&pk.x = __floats2half2_rn(o0, o1);
            *(__half2*)&pk.y = __floats2half2_rn(o2, o3);
            *(__half2*)&pk.z = __floats2half2_rn(o4, o5);
            *(__half2*)&pk.w = __floats2half2_rn(o6, o7);
            ((uint4*)dst)[(size_t)warp * ROW_U4 + p] = pk;
        } else {
            float4* d = (float4*)((float*)dst + (size_t)warp * D_FEAT + p * 8);
            d[0] = make_float4(o0, o1, o2, o3);
            d[1] = make_float4(o4, o5, o6, o7);
        }
    }
}

extern "C" void kernel_launch(void* const* d_in, const int* in_sizes, int n_in,
                              void* d_out, int out_size) {
    const float* x    = (const float*)d_in[0];
    const int*   erow = (const int*)d_in[1];
    const int*   ecol = (const int*)d_in[2];
    const float* ew   = (const float*)d_in[3];
    float*       out  = (float*)d_out;

    uint4 *hA, *hB, *x16;
    int* countPtr;
    cudaGetSymbolAddress((void**)&hA, g_hA);
    cudaGetSymbolAddress((void**)&hB, g_hB);
    cudaGetSymbolAddress((void**)&x16, g_x16);
    cudaGetSymbolAddress((void**)&countPtr, g_count);

    const int TB = 256;
    const int nodeBlocks = (N_NODES + TB - 1) / TB;
    const int quadBlocks = (N_EDGES / 4 + TB - 1) / TB;
    const int cvtBlocks  = (N_NODES * D_FEAT / 8 + TB - 1) / TB;
    const int spmmBlocks = (N_NODES * 32 + TB - 1) / TB;

    // CSR build
    cudaMemsetAsync(countPtr, 0, N_NODES * sizeof(int));
    k_hist<<<quadBlocks, TB>>>((const int4*)erow);
    k_scan1<<<N_SCAN_BLKS, SCAN_BLK>>>();
    k_scan2<<<1, 128>>>();
    k_scan3<<<nodeBlocks, TB>>>();
    k_scatter<<<quadBlocks, TB>>>((const int4*)erow, (const int4*)ecol,
                                  (const float4*)ew);
    k_cvt<<<cvtBlocks, TB>>>((const float4*)x);

    // 10 propagation steps, all fp16 storage, scale c_k = 4^-k (c_10 = 1).
    const uint4* src = x16;
    uint4* bufs[2] = { hA, hB };
    for (int k = 1; k <= K_STEPS; k++) {
        if (k < K_STEPS) {
            float c_k = exp2f(-2.0f * k);
            uint4* dst = bufs[k & 1];
            k_spmm16<true><<<spmmBlocks, TB>>>(src, x, dst, 0.25f, 0.1f * c_k);
            src = dst;
        } else {
            float k1 = exp2f(2.0f * (K_STEPS - 1));   // 1/c_9 = 2^18
            k_spmm16<false><<<spmmBlocks, TB>>>(src, x, out, k1, 0.1f);
        }
    }
}

// round 12
// speedup vs baseline: 1.2187x; 1.0212x over previous
#include <cuda_runtime.h>
#include <cuda_fp16.h>
#include <cstdint>

// APPNP: h <- 0.9 * A@h + 0.1 * x, 10 iterations, edge-list A.
// CSR build, then 10x warp-per-row SpMM in fp16 storage (h_k scaled 4^-k).
// Gather: quarter-warp per edge, one 32-lane LDG.128 covers four 128B fp16
// rows. Edge entries packed to 4B: col(17b) | fixed-point 0.9*w (15b).
// This round: scan3+cvt fused (one fewer launch), uint32 addressing in the
// SpMM hot loop, TB=128 SpMM blocks for finer tail balancing.

#define N_NODES 100000
#define N_EDGES 3200000
#define D_FEAT  64
#define ALPHA   0.1f
#define K_STEPS 10
#define SCAN_BLK 1024
#define N_SCAN_BLKS ((N_NODES + SCAN_BLK - 1) / SCAN_BLK)   // 98
#define ROW_U4 (D_FEAT / 8)   // 8 uint4 (128B) per fp16 row
#define W_SCALE 32768.0f
#define W_INV   (1.0f / 32768.0f)
#define CVT_ELEMS (N_NODES * D_FEAT / 8)   // 800000

// -------- static device scratch (no allocations allowed) --------
__device__ int            g_count[N_NODES];
__device__ int            g_rowptr[N_NODES + 1];
__device__ int            g_bsum[N_SCAN_BLKS];
__device__ int            g_boff[N_SCAN_BLKS];
__device__ unsigned short g_rank[N_EDGES];
__device__ unsigned int   g_cwp[N_EDGES];                   // col<<15 | wfix15
__device__ uint4          g_hA[(size_t)N_NODES * ROW_U4];   // fp16 h ping
__device__ uint4          g_hB[(size_t)N_NODES * ROW_U4];   // fp16 h pong
__device__ uint4          g_x16[(size_t)N_NODES * ROW_U4];  // fp16 copy of x

// -------- CSR build --------
__global__ void k_hist(const int4* __restrict__ erow4) {
    int t = blockIdx.x * blockDim.x + threadIdx.x;
    if (t < N_EDGES / 4) {
        int4 r = erow4[t];
        unsigned short r0 = (unsigned short)atomicAdd(&g_count[r.x], 1);
        unsigned short r1 = (unsigned short)atomicAdd(&g_count[r.y], 1);
        unsigned short r2 = (unsigned short)atomicAdd(&g_count[r.z], 1);
        unsigned short r3 = (unsigned short)atomicAdd(&g_count[r.w], 1);
        ((ushort4*)g_rank)[t] = make_ushort4(r0, r1, r2, r3);
    }
}

__global__ void __launch_bounds__(SCAN_BLK) k_scan1() {
    __shared__ int s[SCAN_BLK];
    int tid = threadIdx.x;
    int i = blockIdx.x * SCAN_BLK + tid;
    int v = (i < N_NODES) ? g_count[i] : 0;
    s[tid] = v;
    __syncthreads();
    #pragma unroll
    for (int off = 1; off < SCAN_BLK; off <<= 1) {
        int t = (tid >= off) ? s[tid - off] : 0;
        __syncthreads();
        s[tid] += t;
        __syncthreads();
    }
    if (i < N_NODES) g_rowptr[i] = s[tid] - v;
    if (tid == SCAN_BLK - 1) g_bsum[blockIdx.x] = s[tid];
}

__global__ void k_scan2() {
    __shared__ int s[128];
    int tid = threadIdx.x;
    int v = (tid < N_SCAN_BLKS) ? g_bsum[tid] : 0;
    s[tid] = v;
    __syncthreads();
    #pragma unroll
    for (int off = 1; off < 128; off <<= 1) {
        int t = (tid >= off) ? s[tid - off] : 0;
        __syncthreads();
        s[tid] += t;
        __syncthreads();
    }
    if (tid < N_SCAN_BLKS) g_boff[tid] = s[tid] - v;
    if (tid == 0) g_rowptr[N_NODES] = N_EDGES;
}

// fused: rowptr fixup (t < N_NODES) + x fp32->fp16 convert (t < CVT_ELEMS)
__global__ void k_scan3_cvt(const float4* __restrict__ xin) {
    int t = blockIdx.x * blockDim.x + threadIdx.x;
    if (t < N_NODES) g_rowptr[t] += g_boff[t >> 10];
    if (t < CVT_ELEMS) {
        float4 a = xin[2 * t], b = xin[2 * t + 1];
        uint4 pk;
        *(__half2*)&pk.x = __floats2half2_rn(a.x, a.y);
        *(__half2*)&pk.y = __floats2half2_rn(a.z, a.w);
        *(__half2*)&pk.z = __floats2half2_rn(b.x, b.y);
        *(__half2*)&pk.w = __floats2half2_rn(b.z, b.w);
        g_x16[t] = pk;
    }
}

__global__ void k_scatter(const int4* __restrict__ erow4,
                          const int4* __restrict__ ecol4,
                          const float4* __restrict__ ew4) {
    int t = blockIdx.x * blockDim.x + threadIdx.x;
    if (t < N_EDGES / 4) {
        int4    r  = erow4[t];
        int4    c  = ecol4[t];
        float4  w  = ew4[t];
        ushort4 rk = ((const ushort4*)g_rank)[t];
        const float s = (1.0f - ALPHA) * W_SCALE;
        unsigned int w0 = (unsigned int)__float2int_rn(s * w.x);
        unsigned int w1 = (unsigned int)__float2int_rn(s * w.y);
        unsigned int w2 = (unsigned int)__float2int_rn(s * w.z);
        unsigned int w3 = (unsigned int)__float2int_rn(s * w.w);
        g_cwp[g_rowptr[r.x] + rk.x] = ((unsigned int)c.x << 15) | w0;
        g_cwp[g_rowptr[r.y] + rk.y] = ((unsigned int)c.y << 15) | w1;
        g_cwp[g_rowptr[r.z] + rk.z] = ((unsigned int)c.z << 15) | w2;
        g_cwp[g_rowptr[r.w] + rk.w] = ((unsigned int)c.w << 15) | w3;
    }
}

// -------- SpMM: warp per row; quarter-warp per edge; LDG.128 gathers -------
// src stored fp16 at scale c_in; writes dst at scale c_out.
// k1 = c_out/c_in, k2 = 0.1*c_out.
template<bool DST_F16>
__global__ void __launch_bounds__(128)
k_spmm16(const uint4* __restrict__ src, const float* __restrict__ x,
         void* __restrict__ dst, float k1, float k2) {
    unsigned int warp = (blockIdx.x * blockDim.x + threadIdx.x) >> 5;
    unsigned int lane = threadIdx.x & 31;
    if (warp >= N_NODES) return;

    unsigned int q = lane >> 3;   // quarter: which edge within each 4-edge step
    unsigned int p = lane & 7;    // feature group: feats p*8 .. p*8+7

    int beg = g_rowptr[warp];
    int end = g_rowptr[warp + 1];

    float acc0 = 0.f, acc1 = 0.f, acc2 = 0.f, acc3 = 0.f;
    float acc4 = 0.f, acc5 = 0.f, acc6 = 0.f, acc7 = 0.f;

    #pragma unroll 4
    for (int e = beg + (int)q; e < end; e += 4) {
        unsigned int cw = g_cwp[e];               // uniform per quarter
        unsigned int c  = cw >> 15;
        float w = (float)(int)(cw & 0x7fffu) * W_INV;   // carries (1-alpha)
        uint4 hv = src[c * ROW_U4 + p];           // 16B of one fp16 row
        float2 f0 = __half22float2(*(const __half2*)&hv.x);
        float2 f1 = __half22float2(*(const __half2*)&hv.y);
        float2 f2 = __half22float2(*(const __half2*)&hv.z);
        float2 f3 = __half22float2(*(const __half2*)&hv.w);
        acc0 = fmaf(w, f0.x, acc0); acc1 = fmaf(w, f0.y, acc1);
        acc2 = fmaf(w, f1.x, acc2); acc3 = fmaf(w, f1.y, acc3);
        acc4 = fmaf(w, f2.x, acc4); acc5 = fmaf(w, f2.y, acc5);
        acc6 = fmaf(w, f3.x, acc6); acc7 = fmaf(w, f3.y, acc7);
    }

    // combine the 4 quarters (disjoint edge subsets, same feature layout)
    #pragma unroll
    for (int d = 8; d <= 16; d <<= 1) {
        acc0 += __shfl_xor_sync(0xffffffffu, acc0, d);
        acc1 += __shfl_xor_sync(0xffffffffu, acc1, d);
        acc2 += __shfl_xor_sync(0xffffffffu, acc2, d);
        acc3 += __shfl_xor_sync(0xffffffffu, acc3, d);
        acc4 += __shfl_xor_sync(0xffffffffu, acc4, d);
        acc5 += __shfl_xor_sync(0xffffffffu, acc5, d);
        acc6 += __shfl_xor_sync(0xffffffffu, acc6, d);
        acc7 += __shfl_xor_sync(0xffffffffu, acc7, d);
    }

    if (lane < 8) {
        const float4* xv = (const float4*)(x + warp * D_FEAT + p * 8);
        float4 xa = xv[0], xb = xv[1];
        float o0 = fmaf(k2, xa.x, k1 * acc0);
        float o1 = fmaf(k2, xa.y, k1 * acc1);
        float o2 = fmaf(k2, xa.z, k1 * acc2);
        float o3 = fmaf(k2, xa.w, k1 * acc3);
        float o4 = fmaf(k2, xb.x, k1 * acc4);
        float o5 = fmaf(k2, xb.y, k1 * acc5);
        float o6 = fmaf(k2, xb.z, k1 * acc6);
        float o7 = fmaf(k2, xb.w, k1 * acc7);
        if (DST_F16) {
            uint4 pk;
            *(__half2*)&pk.x = __floats2half2_rn(o0, o1);
            *(__half2*)&pk.y = __floats2half2_rn(o2, o3);
            *(__half2*)&pk.z = __floats2half2_rn(o4, o5);
            *(__half2*)&pk.w = __floats2half2_rn(o6, o7);
            ((uint4*)dst)[warp * ROW_U4 + p] = pk;
        } else {
            float4* d = (float4*)((float*)dst + warp * D_FEAT + p * 8);
            d[0] = make_float4(o0, o1, o2, o3);
            d[1] = make_float4(o4, o5, o6, o7);
        }
    }
}

extern "C" void kernel_launch(void* const* d_in, const int* in_sizes, int n_in,
                              void* d_out, int out_size) {
    const float* x    = (const float*)d_in[0];
    const int*   erow = (const int*)d_in[1];
    const int*   ecol = (const int*)d_in[2];
    const float* ew   = (const float*)d_in[3];
    float*       out  = (float*)d_out;

    uint4 *hA, *hB, *x16;
    int* countPtr;
    cudaGetSymbolAddress((void**)&hA, g_hA);
    cudaGetSymbolAddress((void**)&hB, g_hB);
    cudaGetSymbolAddress((void**)&x16, g_x16);
    cudaGetSymbolAddress((void**)&countPtr, g_count);

    const int TB = 256;
    const int quadBlocks  = (N_EDGES / 4 + TB - 1) / TB;
    const int fuseBlocks  = (CVT_ELEMS + TB - 1) / TB;   // covers N_NODES too
    const int spmmBlocks  = (N_NODES * 32 + 127) / 128;

    // CSR build
    cudaMemsetAsync(countPtr, 0, N_NODES * sizeof(int));
    k_hist<<<quadBlocks, TB>>>((const int4*)erow);
    k_scan1<<<N_SCAN_BLKS, SCAN_BLK>>>();
    k_scan2<<<1, 128>>>();
    k_scan3_cvt<<<fuseBlocks, TB>>>((const float4*)x);
    k_scatter<<<quadBlocks, TB>>>((const int4*)erow, (const int4*)ecol,
                                  (const float4*)ew);

    // 10 propagation steps, all fp16 storage, scale c_k = 4^-k (c_10 = 1).
    const uint4* src = x16;
    uint4* bufs[2] = { hA, hB };
    for (int k = 1; k <= K_STEPS; k++) {
        if (k < K_STEPS) {
            float c_k = exp2f(-2.0f * k);
            uint4* dst = bufs[k & 1];
            k_spmm16<true><<<spmmBlocks, 128>>>(src, x, dst, 0.25f, 0.1f * c_k);
            src = dst;
        } else {
            float k1 = exp2f(2.0f * (K_STEPS - 1));   // 1/c_9 = 2^18
            k_spmm16<false><<<spmmBlocks, 128>>>(src, x, out, k1, 0.1f);
        }
    }
}